// round 15
// baseline (speedup 1.0000x reference)
#include <cuda_runtime.h>
#include <cuda_fp16.h>
#include <math_constants.h>
#include <cstdint>

#define E_DIM 1024
#define BATCH 2
#define SEQ   2048
#define NHEAD 16
#define HDIM  64
#define MTOT  4096   // BATCH*SEQ

// q pre-scale: 1/sqrt(64) * log2(e)  -> softmax computed with exp2
#define QSCALE 0.18033688011112042f

// ======================= scratch =======================
__device__ __half g_h  [MTOT * E_DIM];
__device__ __half g_o  [MTOT * E_DIM];
__device__ float  g_x2 [MTOT * E_DIM];
__device__ __half g_mb [MTOT * 4 * E_DIM];   // reused: qkv, then mlp hidden
__device__ __half g_wi [3 * E_DIM * E_DIM];
__device__ __half g_wo [E_DIM * E_DIM];
__device__ __half g_wf [4 * E_DIM * E_DIM];
__device__ __half g_wp [E_DIM * 4 * E_DIM];

__device__ __forceinline__ uint32_t smem_u32(const void* p) {
    uint32_t a;
    asm("{ .reg .u64 t; cvta.to.shared.u64 t, %1; cvt.u32.u64 %0, t; }" : "=r"(a) : "l"(p));
    return a;
}
__device__ __forceinline__ void ldsm_x4(uint32_t (&r)[4], uint32_t addr) {
    asm volatile("ldmatrix.sync.aligned.m8n8.x4.shared.b16 {%0,%1,%2,%3}, [%4];"
                 : "=r"(r[0]), "=r"(r[1]), "=r"(r[2]), "=r"(r[3]) : "r"(addr));
}
__device__ __forceinline__ void ldsm_x4_trans(uint32_t (&r)[4], uint32_t addr) {
    asm volatile("ldmatrix.sync.aligned.m8n8.x4.trans.shared.b16 {%0,%1,%2,%3}, [%4];"
                 : "=r"(r[0]), "=r"(r[1]), "=r"(r[2]), "=r"(r[3]) : "r"(addr));
}
__device__ __forceinline__ void mma16816(float (&d)[4], const uint32_t (&a)[4],
                                         uint32_t b0, uint32_t b1) {
    asm volatile("mma.sync.aligned.m16n8k16.row.col.f32.f16.f16.f32 "
                 "{%0,%1,%2,%3}, {%4,%5,%6,%7}, {%8,%9}, {%0,%1,%2,%3};"
                 : "+f"(d[0]), "+f"(d[1]), "+f"(d[2]), "+f"(d[3])
                 : "r"(a[0]), "r"(a[1]), "r"(a[2]), "r"(a[3]), "r"(b0), "r"(b1));
}
__device__ __forceinline__ void cp_async16(uint32_t saddr, const void* gaddr) {
    asm volatile("cp.async.cg.shared.global [%0], [%1], 16;" :: "r"(saddr), "l"(gaddr));
}
__device__ __forceinline__ void cp_commit() {
    asm volatile("cp.async.commit_group;" ::: "memory");
}
template<int N> __device__ __forceinline__ void cp_wait() {
    asm volatile("cp.async.wait_group %0;" :: "n"(N) : "memory");
}

// ======================= fused preprocessing: weight cvt + LN1 =======================
#define WI_N4 (3 * E_DIM * E_DIM / 4)
#define WO_N4 (E_DIM * E_DIM / 4)
#define WF_N4 (4 * E_DIM * E_DIM / 4)
#define WP_N4 (4 * E_DIM * E_DIM / 4)
#define CVT_TOT (WI_N4 + WO_N4 + WF_N4 + WP_N4)
#define CVT_BLOCKS 2048

__device__ __forceinline__ void ln_row(const float* __restrict__ x,
                                       __half* __restrict__ y,
                                       int row, int tid) {
    __shared__ float rs[8], rq[8];
    float4 v = ((const float4*)(x + (size_t)row * E_DIM))[tid];
    float s  = v.x + v.y + v.z + v.w;
    float sq = v.x*v.x + v.y*v.y + v.z*v.z + v.w*v.w;
#pragma unroll
    for (int o = 16; o; o >>= 1) {
        s  += __shfl_xor_sync(0xffffffffu, s,  o);
        sq += __shfl_xor_sync(0xffffffffu, sq, o);
    }
    if ((tid & 31) == 0) { rs[tid >> 5] = s; rq[tid >> 5] = sq; }
    __syncthreads();
    if (tid < 32) {
        s  = (tid < 8) ? rs[tid] : 0.f;
        sq = (tid < 8) ? rq[tid] : 0.f;
#pragma unroll
        for (int o = 4; o; o >>= 1) {
            s  += __shfl_xor_sync(0xffffffffu, s,  o);
            sq += __shfl_xor_sync(0xffffffffu, sq, o);
        }
        if (tid == 0) { rs[0] = s; rq[0] = sq; }
    }
    __syncthreads();
    const float mean = rs[0] * (1.0f / E_DIM);
    const float var  = rq[0] * (1.0f / E_DIM) - mean * mean;
    const float rstd = rsqrtf(var + 1e-5f);
    __half2* p = (__half2*)&y[(size_t)row * E_DIM + tid * 4];
    p[0] = __halves2half2(__float2half_rn((v.x - mean) * rstd),
                          __float2half_rn((v.y - mean) * rstd));
    p[1] = __halves2half2(__float2half_rn((v.z - mean) * rstd),
                          __float2half_rn((v.w - mean) * rstd));
}

__global__ __launch_bounds__(256) void ln_kernel(const float* __restrict__ x,
                                                 __half* __restrict__ y) {
    ln_row(x, y, blockIdx.x, threadIdx.x);
}

// blocks [0, MTOT): LN rows of x.  blocks [MTOT, MTOT+CVT_BLOCKS): weight cvt.
__global__ __launch_bounds__(256) void pre_kernel(
    const float* __restrict__ x, __half* __restrict__ hb,
    const float* __restrict__ w_in, const float* __restrict__ w_out,
    const float* __restrict__ w_fc, const float* __restrict__ w_proj,
    __half* __restrict__ wi, __half* __restrict__ wo,
    __half* __restrict__ wf, __half* __restrict__ wp)
{
    if (blockIdx.x < MTOT) {
        ln_row(x, hb, blockIdx.x, threadIdx.x);
        return;
    }
    const int bid = blockIdx.x - MTOT;
    const int stride = CVT_BLOCKS * 256;
    for (int i = bid * 256 + threadIdx.x; i < CVT_TOT; i += stride) {
        const float* src; __half* dst; int j = i;
        if (j < WI_N4)                { src = w_in;   dst = wi; }
        else if ((j -= WI_N4) < WO_N4){ src = w_out;  dst = wo; }
        else if ((j -= WO_N4) < WF_N4){ src = w_fc;   dst = wf; }
        else { j -= WF_N4;              src = w_proj; dst = wp; }
        float4 v = ((const float4*)src)[j];
        __half2* p = (__half2*)&dst[(size_t)j * 4];
        p[0] = __halves2half2(__float2half_rn(v.x), __float2half_rn(v.y));
        p[1] = __halves2half2(__float2half_rn(v.z), __float2half_rn(v.w));
    }
}

// ======================= fp16 single-pass tensor GEMM (R8 config) =======================
// C[M,N] = A[M,K] * B[N,K]^T
// MODE 1: relu(+bias)->f16 | 2: +res fp32 | 3: +bias+res fp32 | 4: ->f16 (cols<E_DIM *= QSCALE)
#define TILE_BYTES  16384               // 128 rows x 128 bytes (64 fp16)
#define STAGE_BYTES (2 * TILE_BYTES)    // A, B
#define GEMM_STAGES 3
#define GEMM_SMEM   (GEMM_STAGES * STAGE_BYTES)   // 96 KB -> 2 CTAs/SM

template<int MODE>
__global__ __launch_bounds__(256, 2) void gemm_tc(
    const __half* __restrict__ A, const __half* __restrict__ B,
    const float* __restrict__ bias, const float* __restrict__ res,
    float* __restrict__ Cf, __half* __restrict__ Ch,
    int M, int N, int K)
{
    extern __shared__ char smem[];
    const uint32_t sbase = smem_u32(smem);
    const int tid  = threadIdx.x;
    const int wid  = tid >> 5;
    const int lane = tid & 31;
    const int row0 = blockIdx.y * 128;
    const int col0 = blockIdx.x * 128;
    const int wm = (wid & 1) * 64;
    const int wn = (wid >> 1) * 32;

    float acc[4][4][4];
#pragma unroll
    for (int i = 0; i < 4; i++)
#pragma unroll
        for (int j = 0; j < 4; j++)
#pragma unroll
            for (int k = 0; k < 4; k++) acc[i][j][k] = 0.f;

    const int NC = K >> 6;

    auto issue_stage = [&](int c) {
        const uint32_t st = sbase + (c % GEMM_STAGES) * STAGE_BYTES;
        const int k0 = c << 6;
#pragma unroll
        for (int t = 0; t < 2; t++) {
            const __half* g = t ? B : A;
            const int rbase = t ? col0 : row0;
            const uint32_t tb = st + t * TILE_BYTES;
#pragma unroll
            for (int i = 0; i < 4; i++) {
                const int idx = tid + i * 256;
                const int r = idx >> 3, cc = idx & 7;
                cp_async16(tb + r * 128 + ((cc ^ (r & 7)) << 4),
                           g + (size_t)(rbase + r) * K + k0 + cc * 8);
            }
        }
        cp_commit();
    };

    issue_stage(0);
    if (NC > 1) issue_stage(1);

    for (int c = 0; c < NC; c++) {
        if (c < NC - 1) cp_wait<1>();
        else            cp_wait<0>();
        __syncthreads();
        if (c + 2 < NC) issue_stage(c + 2);

        const uint32_t st = sbase + (c % GEMM_STAGES) * STAGE_BYTES;
        const uint32_t sA = st;
        const uint32_t sB = st + TILE_BYTES;
        const int g  = lane >> 3;
        const int lr = lane & 7;

#pragma unroll
        for (int ks = 0; ks < 4; ks++) {
            const int kc0 = ks * 2;
            uint32_t af[4][4], bf[4][2];
#pragma unroll
            for (int mt = 0; mt < 4; mt++) {
                const int row = wm + mt * 16 + lr + (g & 1) * 8;
                const int ch  = kc0 + (g >> 1);
                const uint32_t off = row * 128 + ((ch ^ (row & 7)) << 4);
                ldsm_x4(af[mt], sA + off);
            }
#pragma unroll
            for (int np = 0; np < 2; np++) {
                const int row = wn + np * 16 + lr + (g >> 1) * 8;
                const int ch  = kc0 + (g & 1);
                const uint32_t off = row * 128 + ((ch ^ (row & 7)) << 4);
                uint32_t t0[4];
                ldsm_x4(t0, sB + off);
                bf[np*2][0] = t0[0]; bf[np*2][1] = t0[1];
                bf[np*2+1][0] = t0[2]; bf[np*2+1][1] = t0[3];
            }
#pragma unroll
            for (int mt = 0; mt < 4; mt++)
#pragma unroll
                for (int nt = 0; nt < 4; nt++)
                    mma16816(acc[mt][nt], af[mt], bf[nt][0], bf[nt][1]);
        }
    }

#pragma unroll
    for (int mt = 0; mt < 4; mt++) {
#pragma unroll
        for (int nt = 0; nt < 4; nt++) {
            const int r0 = row0 + wm + mt * 16 + (lane >> 2);
            const int r1 = r0 + 8;
            const int cc = col0 + wn + nt * 8 + (lane & 3) * 2;
            float v0 = acc[mt][nt][0], v1 = acc[mt][nt][1];
            float v2 = acc[mt][nt][2], v3 = acc[mt][nt][3];
            if (MODE == 1 || MODE == 3) {
                const float b0 = bias[cc], b1 = bias[cc + 1];
                v0 += b0; v1 += b1; v2 += b0; v3 += b1;
            }
            if (MODE == 1) {
                v0 = fmaxf(v0, 0.f); v1 = fmaxf(v1, 0.f);
                v2 = fmaxf(v2, 0.f); v3 = fmaxf(v3, 0.f);
            }
            if (MODE == 2 || MODE == 3) {
                float2 ra = *(const float2*)&res[(size_t)r0 * N + cc];
                float2 rb = *(const float2*)&res[(size_t)r1 * N + cc];
                v0 += ra.x; v1 += ra.y; v2 += rb.x; v3 += rb.y;
            }
            if (MODE == 4) {
                if (cc < E_DIM) {
                    v0 *= QSCALE; v1 *= QSCALE; v2 *= QSCALE; v3 *= QSCALE;
                }
            }
            if (MODE == 1 || MODE == 4) {
                *(__half2*)&Ch[(size_t)r0 * N + cc] =
                    __halves2half2(__float2half_rn(v0), __float2half_rn(v1));
                *(__half2*)&Ch[(size_t)r1 * N + cc] =
                    __halves2half2(__float2half_rn(v2), __float2half_rn(v3));
            } else {
                *(float2*)&Cf[(size_t)r0 * N + cc] = {v0, v1};
                *(float2*)&Cf[(size_t)r1 * N + cc] = {v2, v3};
            }
        }
    }
}

// ======================= fp16 MMA causal flash attention (exp2, R12 + PV skip) =========
// CTA: 128 q rows (8 warps x 16). KV tiles of 64 rows, double-buffered.
// smem: Q 16K | stage{K 8K, V 8K} x2 = 48 KB. 2 CTAs/SM.
// q pre-scaled by 0.125*log2(e): S in log2 domain; P via h2exp2.
#define ATT_SMEM 49152

__global__ __launch_bounds__(256, 2) void attn_mma(
    const __half* __restrict__ qkv,
    __half* __restrict__ o)
{
    extern __shared__ char smem[];
    const uint32_t sb = smem_u32(smem);
    const int tid = threadIdx.x, wid = tid >> 5, lane = tid & 31;
    const int qb = (int)gridDim.x - 1 - (int)blockIdx.x;   // longest blocks first
    const int q0 = qb * 128;
    const int h  = blockIdx.y, b = blockIdx.z;
    const int LD = 3 * E_DIM;
    const size_t base = (size_t)b * SEQ * LD + (size_t)h * HDIM;

    const uint32_t sQ = sb;

#pragma unroll
    for (int i = 0; i < 4; i++) {
        const int idx = tid + i * 256;
        const int r = idx >> 3, cc = idx & 7;
        const uint32_t soff = r * 128 + ((cc ^ (r & 7)) << 4);
        cp_async16(sQ + soff, qkv + base + (size_t)(q0 + r) * LD + cc * 8);
    }
    auto issue_kv = [&](int t) {
        const uint32_t st = sb + 16384 + (t & 1) * 16384;
        const int k0 = t * 64;
#pragma unroll
        for (int i = 0; i < 2; i++) {
            const int idx = tid + i * 256;
            const int r = idx >> 3, cc = idx & 7;
            const uint32_t soff = r * 128 + ((cc ^ (r & 7)) << 4);
            cp_async16(st +        soff, qkv + base + E_DIM     + (size_t)(k0 + r) * LD + cc * 8);
            cp_async16(st + 8192 + soff, qkv + base + 2 * E_DIM + (size_t)(k0 + r) * LD + cc * 8);
        }
        cp_commit();
    };
    issue_kv(0);

    const int ntiles = (q0 >> 6) + 2;
    const int g = lane >> 2, tig = lane & 3;
    const int lr = lane & 7, gg = lane >> 3;
    const int warp_rmax = q0 + wid * 16 + 15;

    float oacc[8][4];
#pragma unroll
    for (int j = 0; j < 8; j++)
#pragma unroll
        for (int e = 0; e < 4; e++) oacc[j][e] = 0.f;
    float m0 = -CUDART_INF_F, m1 = -CUDART_INF_F, l0 = 0.f, l1 = 0.f;
    uint32_t qf[4][4];

    for (int t = 0; t < ntiles; t++) {
        if (t + 1 < ntiles) { issue_kv(t + 1); cp_wait<1>(); }
        else                { cp_wait<0>(); }
        __syncthreads();
        if (t == 0) {
            const int row = wid * 16 + lr + (gg & 1) * 8;
#pragma unroll
            for (int kc = 0; kc < 4; kc++) {
                const int ch = kc * 2 + (gg >> 1);
                const uint32_t off = row * 128 + ((ch ^ (row & 7)) << 4);
                ldsm_x4(qf[kc], sQ + off);
            }
        }
        const int k0 = t * 64;
        if (k0 <= warp_rmax) {   // skip fully-masked diagonal tiles for this warp
            const uint32_t sK = sb + 16384 + (t & 1) * 16384;
            const uint32_t sV = sK + 8192;

            // ---- S = Q K^T (log2 domain; q pre-scaled) ----
            float S[8][4];
#pragma unroll
            for (int j = 0; j < 8; j++)
#pragma unroll
                for (int e = 0; e < 4; e++) S[j][e] = 0.f;
#pragma unroll
            for (int kc = 0; kc < 4; kc++) {
                uint32_t bh[8][2];
#pragma unroll
                for (int jp = 0; jp < 4; jp++) {
                    const int row = jp * 16 + lr + (gg >> 1) * 8;
                    const int ch  = kc * 2 + (gg & 1);
                    const uint32_t off = row * 128 + ((ch ^ (row & 7)) << 4);
                    uint32_t t0[4];
                    ldsm_x4(t0, sK + off);
                    bh[jp*2][0] = t0[0]; bh[jp*2][1] = t0[1];
                    bh[jp*2+1][0] = t0[2]; bh[jp*2+1][1] = t0[3];
                }
#pragma unroll
                for (int j = 0; j < 8; j++)
                    mma16816(S[j], qf[kc], bh[j][0], bh[j][1]);
            }

            // ---- causal mask ----
            const int r0 = q0 + wid * 16 + g, r1 = r0 + 8;
            if (k0 + 63 > q0 + wid * 16) {
#pragma unroll
                for (int j = 0; j < 8; j++) {
                    const int c0 = k0 + j * 8 + tig * 2, c1 = c0 + 1;
                    if (c0 > r0) S[j][0] = -CUDART_INF_F;
                    if (c1 > r0) S[j][1] = -CUDART_INF_F;
                    if (c0 > r1) S[j][2] = -CUDART_INF_F;
                    if (c1 > r1) S[j][3] = -CUDART_INF_F;
                }
            }

            // ---- online softmax: pack to fp16x2, exponentiate with h2exp2 ----
            float rx0 = -CUDART_INF_F, rx1 = -CUDART_INF_F;
#pragma unroll
            for (int j = 0; j < 8; j++) {
                rx0 = fmaxf(rx0, fmaxf(S[j][0], S[j][1]));
                rx1 = fmaxf(rx1, fmaxf(S[j][2], S[j][3]));
            }
            rx0 = fmaxf(rx0, __shfl_xor_sync(0xffffffffu, rx0, 1));
            rx0 = fmaxf(rx0, __shfl_xor_sync(0xffffffffu, rx0, 2));
            rx1 = fmaxf(rx1, __shfl_xor_sync(0xffffffffu, rx1, 1));
            rx1 = fmaxf(rx1, __shfl_xor_sync(0xffffffffu, rx1, 2));
            const float nm0 = fmaxf(m0, rx0), nm1 = fmaxf(m1, rx1);
            const float cr0 = exp2f(m0 - nm0), cr1 = exp2f(m1 - nm1);

            uint32_t P01[8], P23[8];
            __half2 sum01 = __float2half2_rn(0.f), sum23 = __float2half2_rn(0.f);
#pragma unroll
            for (int j = 0; j < 8; j++) {
                __half2 e01 = h2exp2(__floats2half2_rn(S[j][0] - nm0, S[j][1] - nm0));
                __half2 e23 = h2exp2(__floats2half2_rn(S[j][2] - nm1, S[j][3] - nm1));
                P01[j] = *(uint32_t*)&e01;
                P23[j] = *(uint32_t*)&e23;
                sum01 = __hadd2(sum01, e01);
                sum23 = __hadd2(sum23, e23);
            }
            float sm0 = __low2float(sum01) + __high2float(sum01);
            float sm1 = __low2float(sum23) + __high2float(sum23);
            sm0 += __shfl_xor_sync(0xffffffffu, sm0, 1);
            sm0 += __shfl_xor_sync(0xffffffffu, sm0, 2);
            sm1 += __shfl_xor_sync(0xffffffffu, sm1, 1);
            sm1 += __shfl_xor_sync(0xffffffffu, sm1, 2);
            l0 = l0 * cr0 + sm0; l1 = l1 * cr1 + sm1;
            m0 = nm0; m1 = nm1;
#pragma unroll
            for (int j = 0; j < 8; j++) {
                oacc[j][0] *= cr0; oacc[j][1] *= cr0;
                oacc[j][2] *= cr1; oacc[j][3] *= cr1;
            }

            // ---- O += P V ---- (skip kc groups whose 16 KV rows are fully masked)
            const int kvr = lane & 15;
            const int jhalf = (lane >> 4);
#pragma unroll
            for (int kc = 0; kc < 4; kc++) {
                if (k0 + kc * 16 > warp_rmax) continue;   // P block is all zeros
                uint32_t vh[8][2];
                const int vr = kc * 16 + kvr;
#pragma unroll
                for (int jp = 0; jp < 4; jp++) {
                    const int jj = jp * 2 + jhalf;
                    const uint32_t off = vr * 128 + ((jj ^ (vr & 7)) << 4);
                    uint32_t v4[4];
                    ldsm_x4_trans(v4, sV + off);
                    vh[jp*2][0]   = v4[0]; vh[jp*2][1]   = v4[1];
                    vh[jp*2+1][0] = v4[2]; vh[jp*2+1][1] = v4[3];
                }
                uint32_t pf[4] = { P01[2*kc], P23[2*kc], P01[2*kc+1], P23[2*kc+1] };
#pragma unroll
                for (int j = 0; j < 8; j++)
                    mma16816(oacc[j], pf, vh[j][0], vh[j][1]);
            }
        }
        __syncthreads();
    }

    // ---- write O (fp16) ----
    const float i0 = 1.0f / l0, i1 = 1.0f / l1;
    const int row0 = q0 + wid * 16 + g;
    const size_t gr0 = ((size_t)b * SEQ + row0) * E_DIM;
    const size_t gr1 = gr0 + 8 * E_DIM;
#pragma unroll
    for (int j = 0; j < 8; j++) {
        const int c = h * HDIM + j * 8 + tig * 2;
        *(__half2*)&o[gr0 + c] = __floats2half2_rn(oacc[j][0] * i0, oacc[j][1] * i0);
        *(__half2*)&o[gr1 + c] = __floats2half2_rn(oacc[j][2] * i1, oacc[j][3] * i1);
    }
}

// ======================= launch =======================
extern "C" void kernel_launch(void* const* d_in, const int* in_sizes, int n_in,
                              void* d_out, int out_size) {
    const float* x      = (const float*)d_in[0];
    const float* w_in   = (const float*)d_in[1];
    const float* w_out  = (const float*)d_in[2];
    const float* w_fc   = (const float*)d_in[3];
    const float* b_fc   = (const float*)d_in[4];
    const float* w_proj = (const float*)d_in[5];
    const float* b_proj = (const float*)d_in[6];
    float* out = (float*)d_out;

    __half *hb, *ob, *mb, *wi, *wo, *wf, *wp;
    float *x2;
    cudaGetSymbolAddress((void**)&hb, g_h);
    cudaGetSymbolAddress((void**)&ob, g_o);
    cudaGetSymbolAddress((void**)&x2, g_x2);
    cudaGetSymbolAddress((void**)&mb, g_mb);
    cudaGetSymbolAddress((void**)&wi, g_wi); cudaGetSymbolAddress((void**)&wo, g_wo);
    cudaGetSymbolAddress((void**)&wf, g_wf); cudaGetSymbolAddress((void**)&wp, g_wp);

    cudaFuncSetAttribute(gemm_tc<1>, cudaFuncAttributeMaxDynamicSharedMemorySize, GEMM_SMEM);
    cudaFuncSetAttribute(gemm_tc<2>, cudaFuncAttributeMaxDynamicSharedMemorySize, GEMM_SMEM);
    cudaFuncSetAttribute(gemm_tc<3>, cudaFuncAttributeMaxDynamicSharedMemorySize, GEMM_SMEM);
    cudaFuncSetAttribute(gemm_tc<4>, cudaFuncAttributeMaxDynamicSharedMemorySize, GEMM_SMEM);
    cudaFuncSetAttribute(attn_mma,   cudaFuncAttributeMaxDynamicSharedMemorySize, ATT_SMEM);

    // fused: LN1 (blocks 0..MTOT) + weight cvt (blocks MTOT..MTOT+CVT_BLOCKS)
    pre_kernel<<<MTOT + CVT_BLOCKS, 256>>>(x, hb, w_in, w_out, w_fc, w_proj,
                                           wi, wo, wf, wp);

    // qkv = h @ w_in^T -> fp16 (q block pre-scaled by QSCALE)
    gemm_tc<4><<<dim3(3 * E_DIM / 128, MTOT / 128), 256, GEMM_SMEM>>>(
        hb, wi, nullptr, nullptr, nullptr, mb, MTOT, 3 * E_DIM, E_DIM);
    // o = causal_attn(qkv) -> fp16
    attn_mma<<<dim3(SEQ / 128, NHEAD, BATCH), 256, ATT_SMEM>>>(mb, ob);
    // x2 = x + o @ w_out^T
    gemm_tc<2><<<dim3(E_DIM / 128, MTOT / 128), 256, GEMM_SMEM>>>(
        ob, wo, nullptr, x, x2, nullptr, MTOT, E_DIM, E_DIM);
    // h = ln(x2) -> fp16
    ln_kernel<<<MTOT, 256>>>(x2, hb);
    // mb = relu(h @ w_fc^T + b_fc) -> fp16
    gemm_tc<1><<<dim3(4 * E_DIM / 128, MTOT / 128), 256, GEMM_SMEM>>>(
        hb, wf, b_fc, nullptr, nullptr, mb, MTOT, 4 * E_DIM, E_DIM);
    // out = mb @ w_proj^T + b_proj + x2
    gemm_tc<3><<<dim3(E_DIM / 128, MTOT / 128), 256, GEMM_SMEM>>>(
        mb, wp, b_proj, x2, out, nullptr, MTOT, E_DIM, 4 * E_DIM);
}

// round 16
// speedup vs baseline: 1.5323x; 1.5323x over previous
#include <cuda_runtime.h>
#include <cuda_fp16.h>
#include <math_constants.h>
#include <cstdint>

#define E_DIM 1024
#define BATCH 2
#define SEQ   2048
#define NHEAD 16
#define HDIM  64
#define MTOT  4096   // BATCH*SEQ

// q pre-scale: 1/sqrt(64) * log2(e)  -> softmax computed with exp2
#define QSCALE 0.18033688011112042f

// ======================= scratch =======================
__device__ __half g_h  [MTOT * E_DIM];
__device__ __half g_o  [MTOT * E_DIM];
__device__ float  g_x2 [MTOT * E_DIM];
__device__ __half g_mb [MTOT * 4 * E_DIM];   // reused: qkv, then mlp hidden
__device__ __half g_wi [3 * E_DIM * E_DIM];
__device__ __half g_wo [E_DIM * E_DIM];
__device__ __half g_wf [4 * E_DIM * E_DIM];
__device__ __half g_wp [E_DIM * 4 * E_DIM];

__device__ __forceinline__ uint32_t smem_u32(const void* p) {
    uint32_t a;
    asm("{ .reg .u64 t; cvta.to.shared.u64 t, %1; cvt.u32.u64 %0, t; }" : "=r"(a) : "l"(p));
    return a;
}
__device__ __forceinline__ void ldsm_x4(uint32_t (&r)[4], uint32_t addr) {
    asm volatile("ldmatrix.sync.aligned.m8n8.x4.shared.b16 {%0,%1,%2,%3}, [%4];"
                 : "=r"(r[0]), "=r"(r[1]), "=r"(r[2]), "=r"(r[3]) : "r"(addr));
}
__device__ __forceinline__ void ldsm_x4_trans(uint32_t (&r)[4], uint32_t addr) {
    asm volatile("ldmatrix.sync.aligned.m8n8.x4.trans.shared.b16 {%0,%1,%2,%3}, [%4];"
                 : "=r"(r[0]), "=r"(r[1]), "=r"(r[2]), "=r"(r[3]) : "r"(addr));
}
__device__ __forceinline__ void mma16816(float (&d)[4], const uint32_t (&a)[4],
                                         uint32_t b0, uint32_t b1) {
    asm volatile("mma.sync.aligned.m16n8k16.row.col.f32.f16.f16.f32 "
                 "{%0,%1,%2,%3}, {%4,%5,%6,%7}, {%8,%9}, {%0,%1,%2,%3};"
                 : "+f"(d[0]), "+f"(d[1]), "+f"(d[2]), "+f"(d[3])
                 : "r"(a[0]), "r"(a[1]), "r"(a[2]), "r"(a[3]), "r"(b0), "r"(b1));
}
__device__ __forceinline__ void cp_async16(uint32_t saddr, const void* gaddr) {
    asm volatile("cp.async.cg.shared.global [%0], [%1], 16;" :: "r"(saddr), "l"(gaddr));
}
__device__ __forceinline__ void cp_commit() {
    asm volatile("cp.async.commit_group;" ::: "memory");
}
template<int N> __device__ __forceinline__ void cp_wait() {
    asm volatile("cp.async.wait_group %0;" :: "n"(N) : "memory");
}

// ======================= fused weight convert =======================
#define WI_N4 (3 * E_DIM * E_DIM / 4)
#define WO_N4 (E_DIM * E_DIM / 4)
#define WF_N4 (4 * E_DIM * E_DIM / 4)
#define WP_N4 (4 * E_DIM * E_DIM / 4)
#define CVT_TOT (WI_N4 + WO_N4 + WF_N4 + WP_N4)

__global__ __launch_bounds__(256) void cvt_all(
    const float* __restrict__ w_in, const float* __restrict__ w_out,
    const float* __restrict__ w_fc, const float* __restrict__ w_proj,
    __half* __restrict__ wi, __half* __restrict__ wo,
    __half* __restrict__ wf, __half* __restrict__ wp)
{
    const int stride = gridDim.x * blockDim.x;
    for (int i = blockIdx.x * blockDim.x + threadIdx.x; i < CVT_TOT; i += stride) {
        const float* src; __half* dst; int j = i;
        if (j < WI_N4)                { src = w_in;   dst = wi; }
        else if ((j -= WI_N4) < WO_N4){ src = w_out;  dst = wo; }
        else if ((j -= WO_N4) < WF_N4){ src = w_fc;   dst = wf; }
        else { j -= WF_N4;              src = w_proj; dst = wp; }
        float4 v = ((const float4*)src)[j];
        __half2* p = (__half2*)&dst[(size_t)j * 4];
        p[0] = __halves2half2(__float2half_rn(v.x), __float2half_rn(v.y));
        p[1] = __halves2half2(__float2half_rn(v.z), __float2half_rn(v.w));
    }
}

// ======================= layernorm (emits fp16) =======================
__global__ __launch_bounds__(256) void ln_kernel(const float* __restrict__ x,
                                                 __half* __restrict__ y) {
    __shared__ float rs[8], rq[8];
    const int row = blockIdx.x;
    const int tid = threadIdx.x;
    float4 v = ((const float4*)(x + (size_t)row * E_DIM))[tid];
    float s  = v.x + v.y + v.z + v.w;
    float sq = v.x*v.x + v.y*v.y + v.z*v.z + v.w*v.w;
#pragma unroll
    for (int o = 16; o; o >>= 1) {
        s  += __shfl_xor_sync(0xffffffffu, s,  o);
        sq += __shfl_xor_sync(0xffffffffu, sq, o);
    }
    if ((tid & 31) == 0) { rs[tid >> 5] = s; rq[tid >> 5] = sq; }
    __syncthreads();
    if (tid < 32) {
        s  = (tid < 8) ? rs[tid] : 0.f;
        sq = (tid < 8) ? rq[tid] : 0.f;
#pragma unroll
        for (int o = 4; o; o >>= 1) {
            s  += __shfl_xor_sync(0xffffffffu, s,  o);
            sq += __shfl_xor_sync(0xffffffffu, sq, o);
        }
        if (tid == 0) { rs[0] = s; rq[0] = sq; }
    }
    __syncthreads();
    const float mean = rs[0] * (1.0f / E_DIM);
    const float var  = rq[0] * (1.0f / E_DIM) - mean * mean;
    const float rstd = rsqrtf(var + 1e-5f);
    __half2* p = (__half2*)&y[(size_t)row * E_DIM + tid * 4];
    p[0] = __halves2half2(__float2half_rn((v.x - mean) * rstd),
                          __float2half_rn((v.y - mean) * rstd));
    p[1] = __halves2half2(__float2half_rn((v.z - mean) * rstd),
                          __float2half_rn((v.w - mean) * rstd));
}

// ======================= fp16 single-pass tensor GEMM (R8 config) =======================
// C[M,N] = A[M,K] * B[N,K]^T
// MODE 1: relu(+bias)->f16 | 2: +res fp32 | 3: +bias+res fp32 | 4: ->f16 (cols<E_DIM *= QSCALE)
#define TILE_BYTES  16384               // 128 rows x 128 bytes (64 fp16)
#define STAGE_BYTES (2 * TILE_BYTES)    // A, B
#define GEMM_STAGES 3
#define GEMM_SMEM   (GEMM_STAGES * STAGE_BYTES)   // 96 KB -> 2 CTAs/SM

template<int MODE>
__global__ __launch_bounds__(256, 2) void gemm_tc(
    const __half* __restrict__ A, const __half* __restrict__ B,
    const float* __restrict__ bias, const float* __restrict__ res,
    float* __restrict__ Cf, __half* __restrict__ Ch,
    int M, int N, int K)
{
    extern __shared__ char smem[];
    const uint32_t sbase = smem_u32(smem);
    const int tid  = threadIdx.x;
    const int wid  = tid >> 5;
    const int lane = tid & 31;
    const int row0 = blockIdx.y * 128;
    const int col0 = blockIdx.x * 128;
    const int wm = (wid & 1) * 64;
    const int wn = (wid >> 1) * 32;

    float acc[4][4][4];
#pragma unroll
    for (int i = 0; i < 4; i++)
#pragma unroll
        for (int j = 0; j < 4; j++)
#pragma unroll
            for (int k = 0; k < 4; k++) acc[i][j][k] = 0.f;

    const int NC = K >> 6;

    auto issue_stage = [&](int c) {
        const uint32_t st = sbase + (c % GEMM_STAGES) * STAGE_BYTES;
        const int k0 = c << 6;
#pragma unroll
        for (int t = 0; t < 2; t++) {
            const __half* g = t ? B : A;
            const int rbase = t ? col0 : row0;
            const uint32_t tb = st + t * TILE_BYTES;
#pragma unroll
            for (int i = 0; i < 4; i++) {
                const int idx = tid + i * 256;
                const int r = idx >> 3, cc = idx & 7;
                cp_async16(tb + r * 128 + ((cc ^ (r & 7)) << 4),
                           g + (size_t)(rbase + r) * K + k0 + cc * 8);
            }
        }
        cp_commit();
    };

    issue_stage(0);
    if (NC > 1) issue_stage(1);

    for (int c = 0; c < NC; c++) {
        if (c < NC - 1) cp_wait<1>();
        else            cp_wait<0>();
        __syncthreads();
        if (c + 2 < NC) issue_stage(c + 2);

        const uint32_t st = sbase + (c % GEMM_STAGES) * STAGE_BYTES;
        const uint32_t sA = st;
        const uint32_t sB = st + TILE_BYTES;
        const int g  = lane >> 3;
        const int lr = lane & 7;

#pragma unroll
        for (int ks = 0; ks < 4; ks++) {
            const int kc0 = ks * 2;
            uint32_t af[4][4], bf[4][2];
#pragma unroll
            for (int mt = 0; mt < 4; mt++) {
                const int row = wm + mt * 16 + lr + (g & 1) * 8;
                const int ch  = kc0 + (g >> 1);
                const uint32_t off = row * 128 + ((ch ^ (row & 7)) << 4);
                ldsm_x4(af[mt], sA + off);
            }
#pragma unroll
            for (int np = 0; np < 2; np++) {
                const int row = wn + np * 16 + lr + (g >> 1) * 8;
                const int ch  = kc0 + (g & 1);
                const uint32_t off = row * 128 + ((ch ^ (row & 7)) << 4);
                uint32_t t0[4];
                ldsm_x4(t0, sB + off);
                bf[np*2][0] = t0[0]; bf[np*2][1] = t0[1];
                bf[np*2+1][0] = t0[2]; bf[np*2+1][1] = t0[3];
            }
#pragma unroll
            for (int mt = 0; mt < 4; mt++)
#pragma unroll
                for (int nt = 0; nt < 4; nt++)
                    mma16816(acc[mt][nt], af[mt], bf[nt][0], bf[nt][1]);
        }
    }

#pragma unroll
    for (int mt = 0; mt < 4; mt++) {
#pragma unroll
        for (int nt = 0; nt < 4; nt++) {
            const int r0 = row0 + wm + mt * 16 + (lane >> 2);
            const int r1 = r0 + 8;
            const int cc = col0 + wn + nt * 8 + (lane & 3) * 2;
            float v0 = acc[mt][nt][0], v1 = acc[mt][nt][1];
            float v2 = acc[mt][nt][2], v3 = acc[mt][nt][3];
            if (MODE == 1 || MODE == 3) {
                const float b0 = bias[cc], b1 = bias[cc + 1];
                v0 += b0; v1 += b1; v2 += b0; v3 += b1;
            }
            if (MODE == 1) {
                v0 = fmaxf(v0, 0.f); v1 = fmaxf(v1, 0.f);
                v2 = fmaxf(v2, 0.f); v3 = fmaxf(v3, 0.f);
            }
            if (MODE == 2 || MODE == 3) {
                float2 ra = *(const float2*)&res[(size_t)r0 * N + cc];
                float2 rb = *(const float2*)&res[(size_t)r1 * N + cc];
                v0 += ra.x; v1 += ra.y; v2 += rb.x; v3 += rb.y;
            }
            if (MODE == 4) {
                // pre-scale q block (cols < E_DIM) for exp2-domain softmax
                if (cc < E_DIM) {
                    v0 *= QSCALE; v1 *= QSCALE; v2 *= QSCALE; v3 *= QSCALE;
                }
            }
            if (MODE == 1 || MODE == 4) {
                *(__half2*)&Ch[(size_t)r0 * N + cc] =
                    __halves2half2(__float2half_rn(v0), __float2half_rn(v1));
                *(__half2*)&Ch[(size_t)r1 * N + cc] =
                    __halves2half2(__float2half_rn(v2), __float2half_rn(v3));
            } else {
                *(float2*)&Cf[(size_t)r0 * N + cc] = {v0, v1};
                *(float2*)&Cf[(size_t)r1 * N + cc] = {v2, v3};
            }
        }
    }
}

// ======================= fp16 MMA causal flash attention (exp2 + h2exp2) ============
// CTA: 128 q rows (8 warps x 16). KV tiles of 64 rows, double-buffered.
// smem: Q 16K | stage{K 8K, V 8K} x2 = 48 KB. 2 CTAs/SM.
// q is pre-scaled by 0.125*log2(e): S is in log2 domain; P computed via h2exp2.
#define ATT_SMEM 49152

__global__ __launch_bounds__(256, 2) void attn_mma(
    const __half* __restrict__ qkv,
    __half* __restrict__ o)
{
    extern __shared__ char smem[];
    const uint32_t sb = smem_u32(smem);
    const int tid = threadIdx.x, wid = tid >> 5, lane = tid & 31;
    const int qb = (int)gridDim.x - 1 - (int)blockIdx.x;   // longest blocks first
    const int q0 = qb * 128;
    const int h  = blockIdx.y, b = blockIdx.z;
    const int LD = 3 * E_DIM;
    const size_t base = (size_t)b * SEQ * LD + (size_t)h * HDIM;

    const uint32_t sQ = sb;

#pragma unroll
    for (int i = 0; i < 4; i++) {
        const int idx = tid + i * 256;
        const int r = idx >> 3, cc = idx & 7;
        const uint32_t soff = r * 128 + ((cc ^ (r & 7)) << 4);
        cp_async16(sQ + soff, qkv + base + (size_t)(q0 + r) * LD + cc * 8);
    }
    auto issue_kv = [&](int t) {
        const uint32_t st = sb + 16384 + (t & 1) * 16384;
        const int k0 = t * 64;
#pragma unroll
        for (int i = 0; i < 2; i++) {
            const int idx = tid + i * 256;
            const int r = idx >> 3, cc = idx & 7;
            const uint32_t soff = r * 128 + ((cc ^ (r & 7)) << 4);
            cp_async16(st +        soff, qkv + base + E_DIM     + (size_t)(k0 + r) * LD + cc * 8);
            cp_async16(st + 8192 + soff, qkv + base + 2 * E_DIM + (size_t)(k0 + r) * LD + cc * 8);
        }
        cp_commit();
    };
    issue_kv(0);

    const int ntiles = (q0 >> 6) + 2;
    const int g = lane >> 2, tig = lane & 3;
    const int lr = lane & 7, gg = lane >> 3;
    const int warp_rmax = q0 + wid * 16 + 15;

    float oacc[8][4];
#pragma unroll
    for (int j = 0; j < 8; j++)
#pragma unroll
        for (int e = 0; e < 4; e++) oacc[j][e] = 0.f;
    float m0 = -CUDART_INF_F, m1 = -CUDART_INF_F, l0 = 0.f, l1 = 0.f;
    uint32_t qf[4][4];

    for (int t = 0; t < ntiles; t++) {
        if (t + 1 < ntiles) { issue_kv(t + 1); cp_wait<1>(); }
        else                { cp_wait<0>(); }
        __syncthreads();
        if (t == 0) {
            const int row = wid * 16 + lr + (gg & 1) * 8;
#pragma unroll
            for (int kc = 0; kc < 4; kc++) {
                const int ch = kc * 2 + (gg >> 1);
                const uint32_t off = row * 128 + ((ch ^ (row & 7)) << 4);
                ldsm_x4(qf[kc], sQ + off);
            }
        }
        const int k0 = t * 64;
        if (k0 <= warp_rmax) {   // skip fully-masked diagonal tiles for this warp
            const uint32_t sK = sb + 16384 + (t & 1) * 16384;
            const uint32_t sV = sK + 8192;

            // ---- S = Q K^T (log2 domain; q pre-scaled) ----
            float S[8][4];
#pragma unroll
            for (int j = 0; j < 8; j++)
#pragma unroll
                for (int e = 0; e < 4; e++) S[j][e] = 0.f;
#pragma unroll
            for (int kc = 0; kc < 4; kc++) {
                uint32_t bh[8][2];
#pragma unroll
                for (int jp = 0; jp < 4; jp++) {
                    const int row = jp * 16 + lr + (gg >> 1) * 8;
                    const int ch  = kc * 2 + (gg & 1);
                    const uint32_t off = row * 128 + ((ch ^ (row & 7)) << 4);
                    uint32_t t0[4];
                    ldsm_x4(t0, sK + off);
                    bh[jp*2][0] = t0[0]; bh[jp*2][1] = t0[1];
                    bh[jp*2+1][0] = t0[2]; bh[jp*2+1][1] = t0[3];
                }
#pragma unroll
                for (int j = 0; j < 8; j++)
                    mma16816(S[j], qf[kc], bh[j][0], bh[j][1]);
            }

            // ---- causal mask ----
            const int r0 = q0 + wid * 16 + g, r1 = r0 + 8;
            if (k0 + 63 > q0 + wid * 16) {
#pragma unroll
                for (int j = 0; j < 8; j++) {
                    const int c0 = k0 + j * 8 + tig * 2, c1 = c0 + 1;
                    if (c0 > r0) S[j][0] = -CUDART_INF_F;
                    if (c1 > r0) S[j][1] = -CUDART_INF_F;
                    if (c0 > r1) S[j][2] = -CUDART_INF_F;
                    if (c1 > r1) S[j][3] = -CUDART_INF_F;
                }
            }

            // ---- online softmax: pack to fp16x2, exponentiate with h2exp2 ----
            float rx0 = -CUDART_INF_F, rx1 = -CUDART_INF_F;
#pragma unroll
            for (int j = 0; j < 8; j++) {
                rx0 = fmaxf(rx0, fmaxf(S[j][0], S[j][1]));
                rx1 = fmaxf(rx1, fmaxf(S[j][2], S[j][3]));
            }
            rx0 = fmaxf(rx0, __shfl_xor_sync(0xffffffffu, rx0, 1));
            rx0 = fmaxf(rx0, __shfl_xor_sync(0xffffffffu, rx0, 2));
            rx1 = fmaxf(rx1, __shfl_xor_sync(0xffffffffu, rx1, 1));
            rx1 = fmaxf(rx1, __shfl_xor_sync(0xffffffffu, rx1, 2));
            const float nm0 = fmaxf(m0, rx0), nm1 = fmaxf(m1, rx1);
            const float cr0 = exp2f(m0 - nm0), cr1 = exp2f(m1 - nm1);

            uint32_t P01[8], P23[8];
            __half2 sum01 = __float2half2_rn(0.f), sum23 = __float2half2_rn(0.f);
#pragma unroll
            for (int j = 0; j < 8; j++) {
                __half2 e01 = h2exp2(__floats2half2_rn(S[j][0] - nm0, S[j][1] - nm0));
                __half2 e23 = h2exp2(__floats2half2_rn(S[j][2] - nm1, S[j][3] - nm1));
                P01[j] = *(uint32_t*)&e01;
                P23[j] = *(uint32_t*)&e23;
                sum01 = __hadd2(sum01, e01);
                sum23 = __hadd2(sum23, e23);
            }
            float sm0 = __low2float(sum01) + __high2float(sum01);
            float sm1 = __low2float(sum23) + __high2float(sum23);
            sm0 += __shfl_xor_sync(0xffffffffu, sm0, 1);
            sm0 += __shfl_xor_sync(0xffffffffu, sm0, 2);
            sm1 += __shfl_xor_sync(0xffffffffu, sm1, 1);
            sm1 += __shfl_xor_sync(0xffffffffu, sm1, 2);
            l0 = l0 * cr0 + sm0; l1 = l1 * cr1 + sm1;
            m0 = nm0; m1 = nm1;
#pragma unroll
            for (int j = 0; j < 8; j++) {
                oacc[j][0] *= cr0; oacc[j][1] *= cr0;
                oacc[j][2] *= cr1; oacc[j][3] *= cr1;
            }

            // ---- O += P V ---- (V fragments via ldsm.x4.trans)
            const int kvr = lane & 15;
            const int jhalf = (lane >> 4);
#pragma unroll
            for (int kc = 0; kc < 4; kc++) {
                uint32_t vh[8][2];
                const int vr = kc * 16 + kvr;
#pragma unroll
                for (int jp = 0; jp < 4; jp++) {
                    const int jj = jp * 2 + jhalf;
                    const uint32_t off = vr * 128 + ((jj ^ (vr & 7)) << 4);
                    uint32_t v4[4];
                    ldsm_x4_trans(v4, sV + off);
                    vh[jp*2][0]   = v4[0]; vh[jp*2][1]   = v4[1];
                    vh[jp*2+1][0] = v4[2]; vh[jp*2+1][1] = v4[3];
                }
                uint32_t pf[4] = { P01[2*kc], P23[2*kc], P01[2*kc+1], P23[2*kc+1] };
#pragma unroll
                for (int j = 0; j < 8; j++)
                    mma16816(oacc[j], pf, vh[j][0], vh[j][1]);
            }
        }
        __syncthreads();
    }

    // ---- write O (fp16) ----
    const float i0 = 1.0f / l0, i1 = 1.0f / l1;
    const int row0 = q0 + wid * 16 + g;
    const size_t gr0 = ((size_t)b * SEQ + row0) * E_DIM;
    const size_t gr1 = gr0 + 8 * E_DIM;
#pragma unroll
    for (int j = 0; j < 8; j++) {
        const int c = h * HDIM + j * 8 + tig * 2;
        *(__half2*)&o[gr0 + c] = __floats2half2_rn(oacc[j][0] * i0, oacc[j][1] * i0);
        *(__half2*)&o[gr1 + c] = __floats2half2_rn(oacc[j][2] * i1, oacc[j][3] * i1);
    }
}

// ======================= launch =======================
extern "C" void kernel_launch(void* const* d_in, const int* in_sizes, int n_in,
                              void* d_out, int out_size) {
    const float* x      = (const float*)d_in[0];
    const float* w_in   = (const float*)d_in[1];
    const float* w_out  = (const float*)d_in[2];
    const float* w_fc   = (const float*)d_in[3];
    const float* b_fc   = (const float*)d_in[4];
    const float* w_proj = (const float*)d_in[5];
    const float* b_proj = (const float*)d_in[6];
    float* out = (float*)d_out;

    __half *hb, *ob, *mb, *wi, *wo, *wf, *wp;
    float *x2;
    cudaGetSymbolAddress((void**)&hb, g_h);
    cudaGetSymbolAddress((void**)&ob, g_o);
    cudaGetSymbolAddress((void**)&x2, g_x2);
    cudaGetSymbolAddress((void**)&mb, g_mb);
    cudaGetSymbolAddress((void**)&wi, g_wi); cudaGetSymbolAddress((void**)&wo, g_wo);
    cudaGetSymbolAddress((void**)&wf, g_wf); cudaGetSymbolAddress((void**)&wp, g_wp);

    cudaFuncSetAttribute(gemm_tc<1>, cudaFuncAttributeMaxDynamicSharedMemorySize, GEMM_SMEM);
    cudaFuncSetAttribute(gemm_tc<2>, cudaFuncAttributeMaxDynamicSharedMemorySize, GEMM_SMEM);
    cudaFuncSetAttribute(gemm_tc<3>, cudaFuncAttributeMaxDynamicSharedMemorySize, GEMM_SMEM);
    cudaFuncSetAttribute(gemm_tc<4>, cudaFuncAttributeMaxDynamicSharedMemorySize, GEMM_SMEM);
    cudaFuncSetAttribute(attn_mma,   cudaFuncAttributeMaxDynamicSharedMemorySize, ATT_SMEM);

    cvt_all<<<2048, 256>>>(w_in, w_out, w_fc, w_proj, wi, wo, wf, wp);

    // h = ln(x) -> fp16
    ln_kernel<<<MTOT, 256>>>(x, hb);
    // qkv = h @ w_in^T -> fp16 (q block pre-scaled by QSCALE)
    gemm_tc<4><<<dim3(3 * E_DIM / 128, MTOT / 128), 256, GEMM_SMEM>>>(
        hb, wi, nullptr, nullptr, nullptr, mb, MTOT, 3 * E_DIM, E_DIM);
    // o = causal_attn(qkv) -> fp16
    attn_mma<<<dim3(SEQ / 128, NHEAD, BATCH), 256, ATT_SMEM>>>(mb, ob);
    // x2 = x + o @ w_out^T
    gemm_tc<2><<<dim3(E_DIM / 128, MTOT / 128), 256, GEMM_SMEM>>>(
        ob, wo, nullptr, x, x2, nullptr, MTOT, E_DIM, E_DIM);
    // h = ln(x2) -> fp16
    ln_kernel<<<MTOT, 256>>>(x2, hb);
    // mb = relu(h @ w_fc^T + b_fc) -> fp16
    gemm_tc<1><<<dim3(4 * E_DIM / 128, MTOT / 128), 256, GEMM_SMEM>>>(
        hb, wf, b_fc, nullptr, nullptr, mb, MTOT, 4 * E_DIM, E_DIM);
    // out = mb @ w_proj^T + b_proj + x2
    gemm_tc<3><<<dim3(E_DIM / 128, MTOT / 128), 256, GEMM_SMEM>>>(
        mb, wp, b_proj, x2, out, nullptr, MTOT, E_DIM, 4 * E_DIM);
}